// round 2
// baseline (speedup 1.0000x reference)
#include <cuda_runtime.h>
#include <cstdint>

#define DIN     16
#define DOUT    99
#define CH      128
#define NEDGE   4096
#define MAXNNZ  1024
#define EPB     2          // edges per block
#define TPB     128        // threads per block (each thread: 2 channels)

// ---------------- device scratch (no allocations allowed) ----------------
__device__ int   g_mu[MAXNNZ];        // mu1 | (mu2 << 8), sorted by mu3
__device__ float g_cg[MAXNNZ];        // cg, sorted by mu3
__device__ int   g_start[DOUT + 1];   // segment offsets per output index

// ---------------- prep: deterministic counting sort by mu3 ----------------
__global__ void prep_kernel(const int* __restrict__ mu1,
                            const int* __restrict__ mu2,
                            const int* __restrict__ mu3,
                            const float* __restrict__ cg,
                            int nnz)
{
    __shared__ int s_mu3[MAXNNZ];
    __shared__ int s_cnt[DOUT + 1];

    const int tid = threadIdx.x;
    if (nnz > MAXNNZ) nnz = MAXNNZ;   // safety clamp

    for (int i = tid; i <= DOUT; i += blockDim.x) s_cnt[i] = 0;
    __syncthreads();

    for (int k = tid; k < nnz; k += blockDim.x) {
        int m3 = mu3[k];
        s_mu3[k] = m3;
        atomicAdd(&s_cnt[m3 + 1], 1);
    }
    __syncthreads();

    if (tid == 0) {
        // inclusive scan: s_cnt[i] becomes start offset of segment i
        int acc = 0;
        for (int i = 0; i <= DOUT; i++) { acc += s_cnt[i]; s_cnt[i] = acc; }
    }
    __syncthreads();

    // deterministic rank: number of earlier entries with same mu3
    for (int k = tid; k < nnz; k += blockDim.x) {
        int m3 = s_mu3[k];
        int rank = 0;
        for (int j = 0; j < k; j++) rank += (s_mu3[j] == m3) ? 1 : 0;
        int pos = s_cnt[m3] + rank;
        g_mu[pos] = (mu1[k] & 0xFF) | ((mu2[k] & 0xFF) << 8);
        g_cg[pos] = cg[k];
    }
    for (int i = tid; i <= DOUT; i += blockDim.x) g_start[i] = s_cnt[i];
}

// ---------------- main tensor-product kernel ----------------
// grid = NEDGE/EPB blocks, TPB threads. Thread t handles edge (t>>6),
// channels 2*(t&63) .. +1 as a float2.
__global__ void __launch_bounds__(TPB) tp_kernel(const float* __restrict__ x,
                                                 const float* __restrict__ y,
                                                 float* __restrict__ out,
                                                 int nnz)
{
    __shared__ float sx[EPB * DIN * CH];
    __shared__ float sy[EPB * DIN * CH];
    __shared__ int   s_mu[MAXNNZ];
    __shared__ float s_cg[MAXNNZ];
    __shared__ int   s_start[DOUT + 1];

    const int tid = threadIdx.x;
    const int n0  = blockIdx.x * EPB;

    // stage metadata (L2-resident after first wave)
    for (int i = tid; i < nnz; i += TPB) { s_mu[i] = g_mu[i]; s_cg[i] = g_cg[i]; }
    for (int i = tid; i <= DOUT; i += TPB) s_start[i] = g_start[i];

    // stage x/y tiles for EPB contiguous edges: EPB*DIN*CH floats each
    {
        const float4* gx = (const float4*)(x + (size_t)n0 * DIN * CH);
        const float4* gy = (const float4*)(y + (size_t)n0 * DIN * CH);
        float4* sx4 = (float4*)sx;
        float4* sy4 = (float4*)sy;
        const int NV = EPB * DIN * CH / 4;   // 1024
        #pragma unroll
        for (int i = tid; i < NV; i += TPB) { sx4[i] = gx[i]; sy4[i] = gy[i]; }
    }
    __syncthreads();

    const int e   = tid >> 6;          // local edge 0/1
    const int c2  = (tid & 63) * 2;    // starting channel (float2)
    const float* mx = sx + e * DIN * CH + c2;
    const float* my = sy + e * DIN * CH + c2;
    float* dst = out + ((size_t)(n0 + e) * DOUT) * CH + c2;

    for (int m3 = 0; m3 < DOUT; m3++) {
        const int kb = s_start[m3];
        const int ke = s_start[m3 + 1];
        float ax = 0.f, ay = 0.f;
        for (int k = kb; k < ke; k++) {
            const int   mu  = s_mu[k];
            const float cgv = s_cg[k];
            const float2 xv = *(const float2*)(mx + (mu & 0xFF) * CH);
            const float2 yv = *(const float2*)(my + (mu >> 8) * CH);
            ax = fmaf(cgv * xv.x, yv.x, ax);
            ay = fmaf(cgv * xv.y, yv.y, ay);
        }
        float2 r; r.x = ax; r.y = ay;
        __stcs((float2*)(dst + m3 * CH), r);   // streaming store, bypass L2 retention
    }
}

// ---------------- launch ----------------
extern "C" void kernel_launch(void* const* d_in, const int* in_sizes, int n_in,
                              void* d_out, int out_size)
{
    const float* x   = (const float*)d_in[0];
    const float* y   = (const float*)d_in[1];
    const int*   mu1 = (const int*)d_in[2];
    const int*   mu2 = (const int*)d_in[3];
    const int*   mu3 = (const int*)d_in[4];
    const float* cg  = (const float*)d_in[5];
    const int    nnz = in_sizes[2];

    float* out = (float*)d_out;

    prep_kernel<<<1, 256>>>(mu1, mu2, mu3, cg, nnz);
    tp_kernel<<<NEDGE / EPB, TPB>>>(x, y, out, nnz);
}

// round 3
// speedup vs baseline: 1.3141x; 1.3141x over previous
#include <cuda_runtime.h>
#include <cstdint>

#define DIN     16
#define DOUT    99
#define CH      128
#define NEDGE   4096
#define MAXNNZ  1024
#define EPB     2          // edges per block
#define TPB     256        // 8 warps: 4 warps per edge (m3-chunked)
#define NCHUNK  4

// ---------------- device scratch (no allocations allowed) ----------------
__device__ int2 g_meta[MAXNNZ];       // {mu1*CH | (mu2*CH)<<16, cg bits}, sorted by mu3
__device__ int  g_start[DOUT + 1];    // segment offsets per output index
__device__ int  g_cm3[NCHUNK + 1];    // m3 chunk boundaries, nnz-balanced

// ---------------- prep: deterministic counting sort by mu3 ----------------
__global__ void prep_kernel(const int* __restrict__ mu1,
                            const int* __restrict__ mu2,
                            const int* __restrict__ mu3,
                            const float* __restrict__ cg,
                            int nnz)
{
    __shared__ int s_mu3[MAXNNZ];
    __shared__ int s_cnt[DOUT + 1];

    const int tid = threadIdx.x;
    if (nnz > MAXNNZ) nnz = MAXNNZ;   // safety clamp

    for (int i = tid; i <= DOUT; i += blockDim.x) s_cnt[i] = 0;
    __syncthreads();

    for (int k = tid; k < nnz; k += blockDim.x) {
        int m3 = mu3[k];
        s_mu3[k] = m3;
        atomicAdd(&s_cnt[m3 + 1], 1);
    }
    __syncthreads();

    if (tid == 0) {
        int acc = 0;
        for (int i = 0; i <= DOUT; i++) { acc += s_cnt[i]; s_cnt[i] = acc; }
    }
    __syncthreads();

    // deterministic rank: number of earlier entries with same mu3
    for (int k = tid; k < nnz; k += blockDim.x) {
        int m3 = s_mu3[k];
        int rank = 0;
        for (int j = 0; j < k; j++) rank += (s_mu3[j] == m3) ? 1 : 0;
        int pos = s_cnt[m3] + rank;
        g_meta[pos] = make_int2((mu1[k] * CH) | ((mu2[k] * CH) << 16),
                                __float_as_int(cg[k]));
    }
    for (int i = tid; i <= DOUT; i += blockDim.x) g_start[i] = s_cnt[i];
    __syncthreads();

    if (tid == 0) {
        // nnz-balanced m3 chunk boundaries for the 4 worker warps per edge
        int total = s_cnt[DOUT];
        g_cm3[0] = 0; g_cm3[NCHUNK] = DOUT;
        for (int c = 1; c < NCHUNK; c++) {
            int target = (total * c) / NCHUNK;
            int m = 0;
            while (m < DOUT && s_cnt[m] < target) m++;
            g_cm3[c] = m;
        }
    }
}

// ---------------- main tensor-product kernel ----------------
// grid = NEDGE/EPB blocks, 256 threads (8 warps).
// warp w: edge = w>>2 (local), m3 chunk = w&3. Lane handles 4 channels (float4).
__global__ void __launch_bounds__(TPB) tp_kernel(const float* __restrict__ x,
                                                 const float* __restrict__ y,
                                                 float* __restrict__ out,
                                                 int nnz)
{
    __shared__ float sx[EPB * DIN * CH];
    __shared__ float sy[EPB * DIN * CH];
    __shared__ int2  s_meta[MAXNNZ];
    __shared__ int   s_start[DOUT + 1];
    __shared__ int   s_cm3[NCHUNK + 1];

    const int tid  = threadIdx.x;
    const int wid  = tid >> 5;
    const int lane = tid & 31;
    const int n0   = blockIdx.x * EPB;

    // stage metadata (L2-resident after first wave)
    for (int i = tid; i < nnz; i += TPB) s_meta[i] = g_meta[i];
    for (int i = tid; i <= DOUT; i += TPB) s_start[i] = g_start[i];
    if (tid <= NCHUNK) s_cm3[tid] = g_cm3[tid];

    // stage x/y tiles for EPB contiguous edges
    {
        const float4* gx = (const float4*)(x + (size_t)n0 * DIN * CH);
        const float4* gy = (const float4*)(y + (size_t)n0 * DIN * CH);
        float4* sx4 = (float4*)sx;
        float4* sy4 = (float4*)sy;
        const int NV = EPB * DIN * CH / 4;   // 1024
        #pragma unroll
        for (int i = tid; i < NV; i += TPB) { sx4[i] = gx[i]; sy4[i] = gy[i]; }
    }
    __syncthreads();

    const int e     = wid >> 2;        // local edge 0/1
    const int chunk = wid & 3;         // m3 chunk for this warp
    const float* mx = sx + e * (DIN * CH) + lane * 4;
    const float* my = sy + e * (DIN * CH) + lane * 4;
    float* dst = out + (size_t)(n0 + e) * DOUT * CH + lane * 4;

    const int m3lo = s_cm3[chunk];
    const int m3hi = s_cm3[chunk + 1];

    int kb = s_start[m3lo];
    for (int m3 = m3lo; m3 < m3hi; m3++) {
        const int ke = s_start[m3 + 1];
        float ax = 0.f, ay = 0.f, az = 0.f, aw = 0.f;
        for (int k = kb; k < ke; k++) {
            const int2 me = s_meta[k];
            const float    cgv = __int_as_float(me.y);
            const unsigned p   = (unsigned)me.x;
            const float4 xv = *(const float4*)(mx + (p & 0xFFFFu));
            const float4 yv = *(const float4*)(my + (p >> 16));
            ax = fmaf(cgv * xv.x, yv.x, ax);
            ay = fmaf(cgv * xv.y, yv.y, ay);
            az = fmaf(cgv * xv.z, yv.z, az);
            aw = fmaf(cgv * xv.w, yv.w, aw);
        }
        kb = ke;
        float4 r; r.x = ax; r.y = ay; r.z = az; r.w = aw;
        __stcs((float4*)(dst + m3 * CH), r);   // streaming store, bypass L2 retention
    }
}

// ---------------- launch ----------------
extern "C" void kernel_launch(void* const* d_in, const int* in_sizes, int n_in,
                              void* d_out, int out_size)
{
    const float* x   = (const float*)d_in[0];
    const float* y   = (const float*)d_in[1];
    const int*   mu1 = (const int*)d_in[2];
    const int*   mu2 = (const int*)d_in[3];
    const int*   mu3 = (const int*)d_in[4];
    const float* cg  = (const float*)d_in[5];
    const int    nnz = in_sizes[2];

    float* out = (float*)d_out;

    prep_kernel<<<1, 256>>>(mu1, mu2, mu3, cg, nnz);
    tp_kernel<<<NEDGE / EPB, TPB>>>(x, y, out, nnz);
}